// round 10
// baseline (speedup 1.0000x reference)
#include <cuda_runtime.h>
#include <cuda_bf16.h>
#include <cstdint>

#define NN 100000
#define EE 1600000
#define NB_SCAN 98
#define ASTR 68              // As row stride (words): conflict-free A-frag loads
#define BSTR 72              // B row stride (words): conflict-free B-frag loads

typedef unsigned int uint32;

// ---------------- persistent device scratch ----------------
__device__ float g_h0[NN * 64];
__device__ float g_h1[NN * 64];
__device__ int   g_deg[NN];          // zeroed at load; re-zeroed by k_segsort each call
__device__ int   g_off[NN + 1];
__device__ int   g_cur[NN];
__device__ int   g_srcs[EE];
__device__ int   g_bsum[NB_SCAN];

// ---------------- CSR build (validated) ----------------
__global__ void k_hist(const int* __restrict__ ei) {
    int e = blockIdx.x * 256 + threadIdx.x;
    if (e < EE) {
        int d = ei[EE + e];
        if (d >= 0 && d < NN) atomicAdd(&g_deg[d], 1);
    }
}
__global__ void k_scan1() {
    __shared__ int sh[1024];
    int t = threadIdx.x;
    int i = blockIdx.x * 1024 + t;
    int v = (i < NN) ? g_deg[i] : 0;
    sh[t] = v;
    __syncthreads();
    for (int d = 1; d < 1024; d <<= 1) {
        int a = (t >= d) ? sh[t - d] : 0;
        __syncthreads();
        sh[t] += a;
        __syncthreads();
    }
    if (i < NN) g_off[i] = sh[t] - v;
    if (t == 1023) g_bsum[blockIdx.x] = sh[1023];
}
__global__ void k_scanadd() {
    __shared__ int pref;
    int i = blockIdx.x * 256 + threadIdx.x;
    if (threadIdx.x == 0) {
        int g = blockIdx.x >> 2;
        int acc = 0;
        for (int b = 0; b < g; b++) acc += g_bsum[b];
        pref = acc;
    }
    __syncthreads();
    if (i < NN) {
        int v = g_off[i] + pref;
        g_off[i] = v;
        g_cur[i] = v;
    }
    if (i == 0) g_off[NN] = EE;
}
__global__ void k_scatter(const int* __restrict__ ei) {
    int e = blockIdx.x * 256 + threadIdx.x;
    if (e < EE) {
        int d = ei[EE + e];
        int s = ei[e];
        if (d >= 0 && d < NN && s >= 0 && s < NN) {
            int p = atomicAdd(&g_cur[d], 1);
            if (p < EE) g_srcs[p] = s;
        }
    }
}
__global__ void k_segsort() {
    int n = blockIdx.x * 256 + threadIdx.x;
    if (n >= NN) return;
    int a = g_off[n], b = g_off[n + 1];
    for (int i = a + 1; i < b; i++) {
        int key = g_srcs[i];
        int j = i - 1;
        while (j >= a && g_srcs[j] > key) { g_srcs[j + 1] = g_srcs[j]; j--; }
        g_srcs[j + 1] = key;
    }
    g_deg[n] = 0;
}

// ---------------- tf32 helpers ----------------
__device__ __forceinline__ uint32 tf32u(float x) {
    uint32 u;
    asm("cvt.rna.tf32.f32 %0, %1;" : "=r"(u) : "f"(x));
    return u;
}
__device__ __forceinline__ void tf32split(float x, uint32& hi, uint32& lo) {
    hi = tf32u(x);
    lo = tf32u(x - __uint_as_float(hi));
}
__device__ __forceinline__ void mma_tf32(float c[4], const uint32 a[4],
                                         uint32 b0, uint32 b1) {
    asm volatile(
        "mma.sync.aligned.m16n8k8.row.col.f32.tf32.tf32.f32 "
        "{%0,%1,%2,%3}, {%4,%5,%6,%7}, {%8,%9}, {%0,%1,%2,%3};"
        : "+f"(c[0]), "+f"(c[1]), "+f"(c[2]), "+f"(c[3])
        : "r"(a[0]), "r"(a[1]), "r"(a[2]), "r"(a[3]), "r"(b0), "r"(b1));
}

// ---------------- fused GIN layer: R9 skeleton + MLP-batched gather ----------------
#define DYN_SMEM ((64 * ASTR + 2 * 64 * BSTR) * 4)

__global__ void __launch_bounds__(256, 3) k_layer(
    const float* __restrict__ x, float* __restrict__ dout,
    const float* __restrict__ W1, const float* __restrict__ b1,
    const float* __restrict__ W2, const float* __restrict__ b2,
    const float* __restrict__ bng, const float* __restrict__ bnb,
    const float* __restrict__ bnm, const float* __restrict__ bnv,
    int layer)
{
    extern __shared__ __align__(16) float dsm[];
    float*  As  = dsm;                       // [64][ASTR]
    uint32* Bhi = (uint32*)(dsm + 64 * ASTR);
    uint32* Blo = Bhi + 64 * BSTR;
    __shared__ float bias1[64], bias2[64], bnsc[64], bnsh[64];

    const float* hin  = (layer == 0) ? x    : ((layer & 1) ? g_h0 : g_h1);
    float*       hout = (layer == 4) ? dout : ((layer & 1) ? g_h1 : g_h0);
    const float* W1p = W1 + layer * 4096;
    const float* W2p = W2 + layer * 4096;

    int tid = threadIdx.x;

    // W1 -> Bhi/Blo (k-major, padded)
    for (int idx = tid; idx < 4096; idx += 256) {
        int k = idx >> 6, n = idx & 63;
        uint32 h, l;
        tf32split(W1p[idx], h, l);
        Bhi[k * BSTR + n] = h;
        Blo[k * BSTR + n] = l;
    }
    if (tid < 64) {
        bias1[tid] = b1[layer * 64 + tid];
        bias2[tid] = b2[layer * 64 + tid];
        if (layer < 4) {
            float sc  = bng[layer * 64 + tid] * rsqrtf(bnv[layer * 64 + tid] + 1e-5f);
            bnsc[tid] = sc;
            bnsh[tid] = bnb[layer * 64 + tid] - bnm[layer * 64 + tid] * sc;
        }
    }

    // ---- aggregation: warp per node; lane l -> feats {2l,2l+1}.
    // 8-deep explicit batching: 8 independent LDG.64 in flight per warp,
    // 4 parallel accumulator chains (deterministic fixed order, srcs sorted).
    int w = tid >> 5, l = tid & 31;
    int base = blockIdx.x * 64;
    for (int r = w; r < 64; r += 8) {
        int n = base + r;
        float ax0 = 0.f, ay0 = 0.f, ax1 = 0.f, ay1 = 0.f;
        float ax2 = 0.f, ay2 = 0.f, ax3 = 0.f, ay3 = 0.f;
        if (n < NN) {
            float2 self = *(const float2*)(hin + n * 64 + 2 * l);
            ax0 = self.x; ay0 = self.y;
            int j = g_off[n], s1 = g_off[n + 1];
            for (; j + 8 <= s1; j += 8) {
                int i0 = g_srcs[j],     i1 = g_srcs[j + 1];
                int i2 = g_srcs[j + 2], i3 = g_srcs[j + 3];
                int i4 = g_srcs[j + 4], i5 = g_srcs[j + 5];
                int i6 = g_srcs[j + 6], i7 = g_srcs[j + 7];
                float2 v0 = __ldg((const float2*)(hin + i0 * 64 + 2 * l));
                float2 v1 = __ldg((const float2*)(hin + i1 * 64 + 2 * l));
                float2 v2 = __ldg((const float2*)(hin + i2 * 64 + 2 * l));
                float2 v3 = __ldg((const float2*)(hin + i3 * 64 + 2 * l));
                float2 v4 = __ldg((const float2*)(hin + i4 * 64 + 2 * l));
                float2 v5 = __ldg((const float2*)(hin + i5 * 64 + 2 * l));
                float2 v6 = __ldg((const float2*)(hin + i6 * 64 + 2 * l));
                float2 v7 = __ldg((const float2*)(hin + i7 * 64 + 2 * l));
                ax0 += v0.x; ay0 += v0.y;  ax1 += v1.x; ay1 += v1.y;
                ax2 += v2.x; ay2 += v2.y;  ax3 += v3.x; ay3 += v3.y;
                ax0 += v4.x; ay0 += v4.y;  ax1 += v5.x; ay1 += v5.y;
                ax2 += v6.x; ay2 += v6.y;  ax3 += v7.x; ay3 += v7.y;
            }
            if (j + 4 <= s1) {
                int i0 = g_srcs[j],     i1 = g_srcs[j + 1];
                int i2 = g_srcs[j + 2], i3 = g_srcs[j + 3];
                float2 v0 = __ldg((const float2*)(hin + i0 * 64 + 2 * l));
                float2 v1 = __ldg((const float2*)(hin + i1 * 64 + 2 * l));
                float2 v2 = __ldg((const float2*)(hin + i2 * 64 + 2 * l));
                float2 v3 = __ldg((const float2*)(hin + i3 * 64 + 2 * l));
                ax0 += v0.x; ay0 += v0.y;  ax1 += v1.x; ay1 += v1.y;
                ax2 += v2.x; ay2 += v2.y;  ax3 += v3.x; ay3 += v3.y;
                j += 4;
            }
            for (; j < s1; j++) {
                int s = g_srcs[j];
                float2 v = __ldg((const float2*)(hin + s * 64 + 2 * l));
                ax0 += v.x; ay0 += v.y;
            }
        }
        float ax = (ax0 + ax1) + (ax2 + ax3);
        float ay = (ay0 + ay1) + (ay2 + ay3);
        *(float2*)(As + r * ASTR + 2 * l) = make_float2(ax, ay);   // row-major z
    }
    __syncthreads();

    // ---- warp/fragment geometry ----
    int lane = tid & 31;
    int grp = lane >> 2, tig = lane & 3;
    int m0 = 16 * (w & 3);                     // warp rows
    int n0 = 32 * (w >> 2);                    // warp cols (4 n8-tiles)

    float c[4][4];

    // ================= GEMM1: C = Z @ W1 (3xTF32) =================
    #pragma unroll
    for (int t = 0; t < 4; t++)
        #pragma unroll
        for (int i = 0; i < 4; i++) c[t][i] = 0.f;

    #pragma unroll
    for (int kc = 0; kc < 8; kc++) {
        int k0 = 8 * kc;
        const float* ap = As + (m0 + grp) * ASTR + k0 + tig;
        float a0 = ap[0], a1 = ap[8 * ASTR], a2 = ap[4], a3 = ap[8 * ASTR + 4];
        uint32 ah[4], al[4];
        tf32split(a0, ah[0], al[0]);
        tf32split(a1, ah[1], al[1]);
        tf32split(a2, ah[2], al[2]);
        tf32split(a3, ah[3], al[3]);
        const uint32* brow0 = Bhi + (k0 + tig) * BSTR;
        const uint32* brow1 = Bhi + (k0 + tig + 4) * BSTR;
        const uint32* crow0 = Blo + (k0 + tig) * BSTR;
        const uint32* crow1 = Blo + (k0 + tig + 4) * BSTR;
        #pragma unroll
        for (int nt = 0; nt < 4; nt++) {
            int nn = n0 + 8 * nt + grp;
            uint32 b0h = brow0[nn], b1h = brow1[nn];
            uint32 b0l = crow0[nn], b1l = crow1[nn];
            mma_tf32(c[nt], ah, b0h, b1h);
            mma_tf32(c[nt], ah, b0l, b1l);
            mma_tf32(c[nt], al, b0h, b1h);
        }
    }
    __syncthreads();

    // ---- epilogue1: Y1 = relu(C + b1) -> As; W2 -> Bhi/Blo ----
    #pragma unroll
    for (int nt = 0; nt < 4; nt++) {
        int col = n0 + 8 * nt + 2 * tig;
        float bv0 = bias1[col], bv1 = bias1[col + 1];
        float y0 = fmaxf(c[nt][0] + bv0, 0.f);
        float y1 = fmaxf(c[nt][1] + bv1, 0.f);
        float y2 = fmaxf(c[nt][2] + bv0, 0.f);
        float y3 = fmaxf(c[nt][3] + bv1, 0.f);
        *(float2*)(As + (m0 + grp) * ASTR + col)     = make_float2(y0, y1);
        *(float2*)(As + (m0 + grp + 8) * ASTR + col) = make_float2(y2, y3);
    }
    for (int idx = tid; idx < 4096; idx += 256) {
        int k = idx >> 6, n = idx & 63;
        uint32 h, lo;
        tf32split(W2p[idx], h, lo);
        Bhi[k * BSTR + n] = h;
        Blo[k * BSTR + n] = lo;
    }
    __syncthreads();

    // ================= GEMM2: C = Y1 @ W2 (3xTF32) =================
    #pragma unroll
    for (int t = 0; t < 4; t++)
        #pragma unroll
        for (int i = 0; i < 4; i++) c[t][i] = 0.f;

    #pragma unroll
    for (int kc = 0; kc < 8; kc++) {
        int k0 = 8 * kc;
        const float* ap = As + (m0 + grp) * ASTR + k0 + tig;
        float a0 = ap[0], a1 = ap[8 * ASTR], a2 = ap[4], a3 = ap[8 * ASTR + 4];
        uint32 ah[4], al[4];
        tf32split(a0, ah[0], al[0]);
        tf32split(a1, ah[1], al[1]);
        tf32split(a2, ah[2], al[2]);
        tf32split(a3, ah[3], al[3]);
        const uint32* brow0 = Bhi + (k0 + tig) * BSTR;
        const uint32* brow1 = Bhi + (k0 + tig + 4) * BSTR;
        const uint32* crow0 = Blo + (k0 + tig) * BSTR;
        const uint32* crow1 = Blo + (k0 + tig + 4) * BSTR;
        #pragma unroll
        for (int nt = 0; nt < 4; nt++) {
            int nn = n0 + 8 * nt + grp;
            uint32 b0h = brow0[nn], b1h = brow1[nn];
            uint32 b0l = crow0[nn], b1l = crow1[nn];
            mma_tf32(c[nt], ah, b0h, b1h);
            mma_tf32(c[nt], ah, b0l, b1l);
            mma_tf32(c[nt], al, b0h, b1h);
        }
    }

    // ---- epilogue2: O = C + b2, BN(eval)+ReLU (layers 0-3), store ----
    {
        int row0 = base + m0 + grp;
        int row1 = row0 + 8;
        #pragma unroll
        for (int nt = 0; nt < 4; nt++) {
            int col = n0 + 8 * nt + 2 * tig;
            float o0 = c[nt][0] + bias2[col];
            float o1 = c[nt][1] + bias2[col + 1];
            float o2 = c[nt][2] + bias2[col];
            float o3 = c[nt][3] + bias2[col + 1];
            if (layer < 4) {
                o0 = fmaxf(o0 * bnsc[col]     + bnsh[col],     0.f);
                o1 = fmaxf(o1 * bnsc[col + 1] + bnsh[col + 1], 0.f);
                o2 = fmaxf(o2 * bnsc[col]     + bnsh[col],     0.f);
                o3 = fmaxf(o3 * bnsc[col + 1] + bnsh[col + 1], 0.f);
            }
            if (row0 < NN) *(float2*)(hout + row0 * 64 + col) = make_float2(o0, o1);
            if (row1 < NN) *(float2*)(hout + row1 * 64 + col) = make_float2(o2, o3);
        }
    }
}

// ---------------- launch ----------------
extern "C" void kernel_launch(void* const* d_in, const int* in_sizes, int n_in,
                              void* d_out, int out_size) {
    const float* x   = (const float*)d_in[0];
    const int*   ei  = (const int*)d_in[1];     // [2, E] int32
    const float* W1  = (const float*)d_in[2];
    const float* b1  = (const float*)d_in[3];
    const float* W2  = (const float*)d_in[4];
    const float* b2  = (const float*)d_in[5];
    const float* bng = (const float*)d_in[6];
    const float* bnb = (const float*)d_in[7];
    const float* bnm = (const float*)d_in[8];
    const float* bnv = (const float*)d_in[9];
    float* out = (float*)d_out;

    cudaFuncSetAttribute(k_layer, cudaFuncAttributeMaxDynamicSharedMemorySize, DYN_SMEM);

    const int gN = (NN + 255) / 256;     // 391
    const int gE = (EE + 255) / 256;     // 6250

    k_hist<<<gE, 256>>>(ei);
    k_scan1<<<NB_SCAN, 1024>>>();
    k_scanadd<<<gN, 256>>>();
    k_scatter<<<gE, 256>>>(ei);
    k_segsort<<<gN, 256>>>();

    const int gL = (NN + 63) / 64;       // 1563
    for (int layer = 0; layer < 5; layer++) {
        k_layer<<<gL, 256, DYN_SMEM>>>(x, out, W1, b1, W2, b2, bng, bnb, bnm, bnv, layer);
    }
}

// round 11
// speedup vs baseline: 1.1926x; 1.1926x over previous
#include <cuda_runtime.h>
#include <cuda_bf16.h>
#include <cstdint>

#define NN 100000
#define EE 1600000
#define NB_SCAN 98
#define ASTR 68              // As row stride (words): conflict-free A-frag loads
#define BSTR 72              // B row stride (words): conflict-free B-frag loads

typedef unsigned int uint32;

// ---------------- persistent device scratch ----------------
__device__ float g_h0[NN * 64];
__device__ float g_h1[NN * 64];
__device__ int   g_deg[NN];          // zeroed at load; re-zeroed by k_segsort each call
__device__ int   g_off[NN + 1];
__device__ int   g_cur[NN];
__device__ int   g_srcs[EE];
__device__ int   g_bsum[NB_SCAN];

// ---------------- CSR build (validated) ----------------
__global__ void k_hist(const int* __restrict__ ei) {
    int e = blockIdx.x * 256 + threadIdx.x;
    if (e < EE) {
        int d = ei[EE + e];
        if (d >= 0 && d < NN) atomicAdd(&g_deg[d], 1);
    }
}
__global__ void k_scan1() {
    __shared__ int sh[1024];
    int t = threadIdx.x;
    int i = blockIdx.x * 1024 + t;
    int v = (i < NN) ? g_deg[i] : 0;
    sh[t] = v;
    __syncthreads();
    for (int d = 1; d < 1024; d <<= 1) {
        int a = (t >= d) ? sh[t - d] : 0;
        __syncthreads();
        sh[t] += a;
        __syncthreads();
    }
    if (i < NN) g_off[i] = sh[t] - v;
    if (t == 1023) g_bsum[blockIdx.x] = sh[1023];
}
__global__ void k_scanadd() {
    __shared__ int pref;
    int i = blockIdx.x * 256 + threadIdx.x;
    if (threadIdx.x == 0) {
        int g = blockIdx.x >> 2;
        int acc = 0;
        for (int b = 0; b < g; b++) acc += g_bsum[b];
        pref = acc;
    }
    __syncthreads();
    if (i < NN) {
        int v = g_off[i] + pref;
        g_off[i] = v;
        g_cur[i] = v;
    }
    if (i == 0) g_off[NN] = EE;
}
__global__ void k_scatter(const int* __restrict__ ei) {
    int e = blockIdx.x * 256 + threadIdx.x;
    if (e < EE) {
        int d = ei[EE + e];
        int s = ei[e];
        if (d >= 0 && d < NN && s >= 0 && s < NN) {
            int p = atomicAdd(&g_cur[d], 1);
            if (p < EE) g_srcs[p] = s;
        }
    }
}
__global__ void k_segsort() {
    int n = blockIdx.x * 256 + threadIdx.x;
    if (n >= NN) return;
    int a = g_off[n], b = g_off[n + 1];
    for (int i = a + 1; i < b; i++) {
        int key = g_srcs[i];
        int j = i - 1;
        while (j >= a && g_srcs[j] > key) { g_srcs[j + 1] = g_srcs[j]; j--; }
        g_srcs[j + 1] = key;
    }
    g_deg[n] = 0;
}

// ---------------- tf32 helpers ----------------
__device__ __forceinline__ uint32 tf32u(float x) {
    uint32 u;
    asm("cvt.rna.tf32.f32 %0, %1;" : "=r"(u) : "f"(x));
    return u;
}
__device__ __forceinline__ void tf32split(float x, uint32& hi, uint32& lo) {
    hi = tf32u(x);
    lo = tf32u(x - __uint_as_float(hi));
}
__device__ __forceinline__ void mma_tf32(float c[4], const uint32 a[4],
                                         uint32 b0, uint32 b1) {
    asm volatile(
        "mma.sync.aligned.m16n8k8.row.col.f32.tf32.tf32.f32 "
        "{%0,%1,%2,%3}, {%4,%5,%6,%7}, {%8,%9}, {%0,%1,%2,%3};"
        : "+f"(c[0]), "+f"(c[1]), "+f"(c[2]), "+f"(c[3])
        : "r"(a[0]), "r"(a[1]), "r"(a[2]), "r"(a[3]), "r"(b0), "r"(b1));
}

// ---------------- fused GIN layer: R9 skeleton, 2-nodes-per-warp float4 gather ----------------
#define DYN_SMEM ((64 * ASTR + 2 * 64 * BSTR) * 4)

__global__ void __launch_bounds__(256) k_layer(
    const float* __restrict__ x, float* __restrict__ dout,
    const float* __restrict__ W1, const float* __restrict__ b1,
    const float* __restrict__ W2, const float* __restrict__ b2,
    const float* __restrict__ bng, const float* __restrict__ bnb,
    const float* __restrict__ bnm, const float* __restrict__ bnv,
    int layer)
{
    extern __shared__ __align__(16) float dsm[];
    float*  As  = dsm;                       // [64][ASTR]
    uint32* Bhi = (uint32*)(dsm + 64 * ASTR);
    uint32* Blo = Bhi + 64 * BSTR;
    __shared__ float bias1[64], bias2[64], bnsc[64], bnsh[64];

    const float* hin  = (layer == 0) ? x    : ((layer & 1) ? g_h0 : g_h1);
    float*       hout = (layer == 4) ? dout : ((layer & 1) ? g_h1 : g_h0);
    const float* W1p = W1 + layer * 4096;
    const float* W2p = W2 + layer * 4096;

    int tid = threadIdx.x;

    // W1 -> Bhi/Blo (k-major, padded)
    for (int idx = tid; idx < 4096; idx += 256) {
        int k = idx >> 6, n = idx & 63;
        uint32 h, l;
        tf32split(W1p[idx], h, l);
        Bhi[k * BSTR + n] = h;
        Blo[k * BSTR + n] = l;
    }
    if (tid < 64) {
        bias1[tid] = b1[layer * 64 + tid];
        bias2[tid] = b2[layer * 64 + tid];
        if (layer < 4) {
            float sc  = bng[layer * 64 + tid] * rsqrtf(bnv[layer * 64 + tid] + 1e-5f);
            bnsc[tid] = sc;
            bnsh[tid] = bnb[layer * 64 + tid] - bnm[layer * 64 + tid] * sc;
        }
    }

    // ---- aggregation: TWO nodes per warp in parallel.
    // Half-warp h (lanes 16h..16h+15) handles node r2+h; lane covers feats
    // {4ls..4ls+3} via LDG.128. Per-node sum order identical to R9 (sorted srcs,
    // sequential) -> bitwise-stable output.
    int w = tid >> 5, l = tid & 31;
    int half = l >> 4, ls = l & 15;
    int base = blockIdx.x * 64;
    for (int r2 = 2 * w; r2 < 64; r2 += 16) {
        int r = r2 + half;
        int n = base + r;
        float4 acc = make_float4(0.f, 0.f, 0.f, 0.f);
        if (n < NN) {
            acc = *(const float4*)(hin + n * 64 + 4 * ls);
            int s0 = g_off[n], s1 = g_off[n + 1];
            #pragma unroll 4
            for (int j = s0; j < s1; j++) {
                int s = g_srcs[j];
                float4 v = __ldg((const float4*)(hin + s * 64 + 4 * ls));
                acc.x += v.x; acc.y += v.y; acc.z += v.z; acc.w += v.w;
            }
        }
        *(float4*)(As + r * ASTR + 4 * ls) = acc;   // row-major z
    }
    __syncthreads();

    // ---- warp/fragment geometry ----
    int lane = tid & 31;
    int grp = lane >> 2, tig = lane & 3;
    int m0 = 16 * (w & 3);                     // warp rows
    int n0 = 32 * (w >> 2);                    // warp cols (4 n8-tiles)

    float c[4][4];

    // ================= GEMM1: C = Z @ W1 (3xTF32) =================
    #pragma unroll
    for (int t = 0; t < 4; t++)
        #pragma unroll
        for (int i = 0; i < 4; i++) c[t][i] = 0.f;

    #pragma unroll
    for (int kc = 0; kc < 8; kc++) {
        int k0 = 8 * kc;
        const float* ap = As + (m0 + grp) * ASTR + k0 + tig;
        float a0 = ap[0], a1 = ap[8 * ASTR], a2 = ap[4], a3 = ap[8 * ASTR + 4];
        uint32 ah[4], al[4];
        tf32split(a0, ah[0], al[0]);
        tf32split(a1, ah[1], al[1]);
        tf32split(a2, ah[2], al[2]);
        tf32split(a3, ah[3], al[3]);
        const uint32* brow0 = Bhi + (k0 + tig) * BSTR;
        const uint32* brow1 = Bhi + (k0 + tig + 4) * BSTR;
        const uint32* crow0 = Blo + (k0 + tig) * BSTR;
        const uint32* crow1 = Blo + (k0 + tig + 4) * BSTR;
        #pragma unroll
        for (int nt = 0; nt < 4; nt++) {
            int nn = n0 + 8 * nt + grp;
            uint32 b0h = brow0[nn], b1h = brow1[nn];
            uint32 b0l = crow0[nn], b1l = crow1[nn];
            mma_tf32(c[nt], ah, b0h, b1h);
            mma_tf32(c[nt], ah, b0l, b1l);
            mma_tf32(c[nt], al, b0h, b1h);
        }
    }
    __syncthreads();

    // ---- epilogue1: Y1 = relu(C + b1) -> As; W2 -> Bhi/Blo ----
    #pragma unroll
    for (int nt = 0; nt < 4; nt++) {
        int col = n0 + 8 * nt + 2 * tig;
        float bv0 = bias1[col], bv1 = bias1[col + 1];
        float y0 = fmaxf(c[nt][0] + bv0, 0.f);
        float y1 = fmaxf(c[nt][1] + bv1, 0.f);
        float y2 = fmaxf(c[nt][2] + bv0, 0.f);
        float y3 = fmaxf(c[nt][3] + bv1, 0.f);
        *(float2*)(As + (m0 + grp) * ASTR + col)     = make_float2(y0, y1);
        *(float2*)(As + (m0 + grp + 8) * ASTR + col) = make_float2(y2, y3);
    }
    for (int idx = tid; idx < 4096; idx += 256) {
        int k = idx >> 6, n = idx & 63;
        uint32 h, lo;
        tf32split(W2p[idx], h, lo);
        Bhi[k * BSTR + n] = h;
        Blo[k * BSTR + n] = lo;
    }
    __syncthreads();

    // ================= GEMM2: C = Y1 @ W2 (3xTF32) =================
    #pragma unroll
    for (int t = 0; t < 4; t++)
        #pragma unroll
        for (int i = 0; i < 4; i++) c[t][i] = 0.f;

    #pragma unroll
    for (int kc = 0; kc < 8; kc++) {
        int k0 = 8 * kc;
        const float* ap = As + (m0 + grp) * ASTR + k0 + tig;
        float a0 = ap[0], a1 = ap[8 * ASTR], a2 = ap[4], a3 = ap[8 * ASTR + 4];
        uint32 ah[4], al[4];
        tf32split(a0, ah[0], al[0]);
        tf32split(a1, ah[1], al[1]);
        tf32split(a2, ah[2], al[2]);
        tf32split(a3, ah[3], al[3]);
        const uint32* brow0 = Bhi + (k0 + tig) * BSTR;
        const uint32* brow1 = Bhi + (k0 + tig + 4) * BSTR;
        const uint32* crow0 = Blo + (k0 + tig) * BSTR;
        const uint32* crow1 = Blo + (k0 + tig + 4) * BSTR;
        #pragma unroll
        for (int nt = 0; nt < 4; nt++) {
            int nn = n0 + 8 * nt + grp;
            uint32 b0h = brow0[nn], b1h = brow1[nn];
            uint32 b0l = crow0[nn], b1l = crow1[nn];
            mma_tf32(c[nt], ah, b0h, b1h);
            mma_tf32(c[nt], ah, b0l, b1l);
            mma_tf32(c[nt], al, b0h, b1h);
        }
    }

    // ---- epilogue2: O = C + b2, BN(eval)+ReLU (layers 0-3), store ----
    {
        int row0 = base + m0 + grp;
        int row1 = row0 + 8;
        #pragma unroll
        for (int nt = 0; nt < 4; nt++) {
            int col = n0 + 8 * nt + 2 * tig;
            float o0 = c[nt][0] + bias2[col];
            float o1 = c[nt][1] + bias2[col + 1];
            float o2 = c[nt][2] + bias2[col];
            float o3 = c[nt][3] + bias2[col + 1];
            if (layer < 4) {
                o0 = fmaxf(o0 * bnsc[col]     + bnsh[col],     0.f);
                o1 = fmaxf(o1 * bnsc[col + 1] + bnsh[col + 1], 0.f);
                o2 = fmaxf(o2 * bnsc[col]     + bnsh[col],     0.f);
                o3 = fmaxf(o3 * bnsc[col + 1] + bnsh[col + 1], 0.f);
            }
            if (row0 < NN) *(float2*)(hout + row0 * 64 + col) = make_float2(o0, o1);
            if (row1 < NN) *(float2*)(hout + row1 * 64 + col) = make_float2(o2, o3);
        }
    }
}

// ---------------- launch ----------------
extern "C" void kernel_launch(void* const* d_in, const int* in_sizes, int n_in,
                              void* d_out, int out_size) {
    const float* x   = (const float*)d_in[0];
    const int*   ei  = (const int*)d_in[1];     // [2, E] int32
    const float* W1  = (const float*)d_in[2];
    const float* b1  = (const float*)d_in[3];
    const float* W2  = (const float*)d_in[4];
    const float* b2  = (const float*)d_in[5];
    const float* bng = (const float*)d_in[6];
    const float* bnb = (const float*)d_in[7];
    const float* bnm = (const float*)d_in[8];
    const float* bnv = (const float*)d_in[9];
    float* out = (float*)d_out;

    cudaFuncSetAttribute(k_layer, cudaFuncAttributeMaxDynamicSharedMemorySize, DYN_SMEM);

    const int gN = (NN + 255) / 256;     // 391
    const int gE = (EE + 255) / 256;     // 6250

    k_hist<<<gE, 256>>>(ei);
    k_scan1<<<NB_SCAN, 1024>>>();
    k_scanadd<<<gN, 256>>>();
    k_scatter<<<gE, 256>>>(ei);
    k_segsort<<<gN, 256>>>();

    const int gL = (NN + 63) / 64;       // 1563
    for (int layer = 0; layer < 5; layer++) {
        k_layer<<<gL, 256, DYN_SMEM>>>(x, out, W1, b1, W2, b2, bng, bnb, bnm, bnv, layer);
    }
}